// round 11
// baseline (speedup 1.0000x reference)
#include <cuda_runtime.h>
#include <math.h>

// Problem dims
#define T_  128
#define B_  64
#define V_  8192
#define H_  2048
#define VH_ 10240   // V_ + H_

#define NCTA 128          // persistent CTAs, one per SM (h-slice of 16)
#define TPB  512
#define HW   16           // h rows per CTA
#define BK   128          // k chunk staged per double-buffer slot
#define WS_STRIDE 2052    // 2048 + 4 pad (16B-aligned rows)
#define AS_STRIDE 132     // 128 + 4 pad (16B-aligned rows)

// State history: g_states[t][b][h]  (64 MB device-global scratch)
__device__ __align__(16) float g_states[(size_t)T_ * B_ * H_];

// Grid barrier state (zero-initialized)
__device__ unsigned g_bar_gen;
__device__ unsigned g_bar_cnt;

// ---------------------------------------------------------------------------
// helpers
// ---------------------------------------------------------------------------
__device__ __forceinline__ void ffma2(unsigned long long& d,
                                      unsigned long long a,
                                      unsigned long long b)
{
    asm("fma.rn.f32x2 %0, %1, %2, %0;" : "+l"(d) : "l"(a), "l"(b));
}

__device__ __forceinline__ float f2_lo(unsigned long long v)
{ return __int_as_float((int)(unsigned)(v & 0xffffffffu)); }
__device__ __forceinline__ float f2_hi(unsigned long long v)
{ return __int_as_float((int)(unsigned)(v >> 32)); }

__device__ __forceinline__ void cp_async16(void* sdst, const void* gsrc)
{
    unsigned sa = (unsigned)__cvta_generic_to_shared(sdst);
    asm volatile("cp.async.cg.shared.global [%0], [%1], 16;\n" :: "r"(sa), "l"(gsrc));
}
__device__ __forceinline__ void cp_commit()
{ asm volatile("cp.async.commit_group;\n"); }
template<int N> __device__ __forceinline__ void cp_wait()
{ asm volatile("cp.async.wait_group %0;\n" :: "n"(N)); }

__device__ __forceinline__ void grid_barrier()
{
    __syncthreads();
    if (threadIdx.x == 0) {
        __threadfence();
        unsigned gen = *(volatile unsigned*)&g_bar_gen;
        unsigned t = atomicAdd(&g_bar_cnt, 1u);
        if (t == NCTA - 1) {
            atomicExch(&g_bar_cnt, 0u);
            __threadfence();
            atomicAdd(&g_bar_gen, 1u);
        } else {
            while (*(volatile unsigned*)&g_bar_gen == gen) { }
        }
        __threadfence();
    }
    __syncthreads();
}

// ---------------------------------------------------------------------------
// Persistent recurrence kernel, v3: 512 threads, 4b x 4h tile, 8-way k-split.
// grid = 128 CTAs x 512 threads. CTA owns h rows [bid*16, bid*16+16).
// Thread mapping: ks = tid&7 (k split), hq = (tid>>3)&3 (h quad),
//                 bq = tid>>5 (b quad).  k interleave: 32 floats/group,
//                 this thread takes floats [g*32 + ks*4, +4).
// ---------------------------------------------------------------------------
extern __shared__ float s_mem[];

__global__ __launch_bounds__(TPB, 1)
void rnn_persistent(const int* __restrict__ tok_all,     // [T_][B_]
                    const float* __restrict__ hidden_w,  // [H_][VH_]
                    const float* __restrict__ hidden_b)  // [H_]
{
    float* ws   = s_mem;                    // [16][WS_STRIDE]
    float* abuf = s_mem + HW * WS_STRIDE;   // 2 x [64][AS_STRIDE]

    const int tid = threadIdx.x;
    const int h0  = blockIdx.x * HW;

    // preload W_hh slice into smem (once)
    for (int r = 0; r < HW; ++r) {
        const float* src = hidden_w + (size_t)(h0 + r) * VH_ + V_;
        float*       dst = ws + r * WS_STRIDE;
        for (int idx = tid; idx < H_ / 4; idx += TPB)
            *(float4*)(dst + idx * 4) = *(const float4*)(src + idx * 4);
    }
    __syncthreads();

    // compute mapping
    const int ks = tid & 7;             // 0..7
    const int hq = (tid >> 3) & 3;      // 0..3
    const int bq = tid >> 5;            // 0..15
    const bool writer = (ks == 0);

    // staging mapping: 64 rows x 32 float4 cols, 512 threads -> 4 elems each
    const int st_c4 = tid & 31;
    const int st_r0 = tid >> 5;         // 0..15 (rows r0 + 16i)

    // biases for this thread's 4 h values (h0 + hq*4 .. +3)
    const float4 bias4 = *(const float4*)(hidden_b + h0 + hq * 4);
    // embedding row pointers
    const float* wrow0 = hidden_w + (size_t)(h0 + hq * 4 + 0) * VH_;
    const float* wrow1 = hidden_w + (size_t)(h0 + hq * 4 + 1) * VH_;
    const float* wrow2 = hidden_w + (size_t)(h0 + hq * 4 + 2) * VH_;
    const float* wrow3 = hidden_w + (size_t)(h0 + hq * 4 + 3) * VH_;

    for (int t = 0; t < T_; ++t) {
        unsigned long long acc[4][4];
#pragma unroll
        for (int bi = 0; bi < 4; ++bi)
#pragma unroll
            for (int hj = 0; hj < 4; ++hj) acc[bi][hj] = 0ull;

        if (t > 0) {
            const float* prev = g_states + (size_t)(t - 1) * B_ * H_;

            // prefetch chunk 0 into buffer 0
            {
                float* buf = abuf;
#pragma unroll
                for (int i = 0; i < 4; ++i) {
                    int r = st_r0 + 16 * i;
                    cp_async16(buf + r * AS_STRIDE + st_c4 * 4,
                               prev + (size_t)r * H_ + st_c4 * 4);
                }
                cp_commit();
            }

            const int NCH = H_ / BK;   // 16
            for (int c = 0; c < NCH; ++c) {
                if (c + 1 < NCH) {
                    float* buf = abuf + ((c + 1) & 1) * (64 * AS_STRIDE);
                    const int k0 = (c + 1) * BK;
#pragma unroll
                    for (int i = 0; i < 4; ++i) {
                        int r = st_r0 + 16 * i;
                        cp_async16(buf + r * AS_STRIDE + st_c4 * 4,
                                   prev + (size_t)r * H_ + k0 + st_c4 * 4);
                    }
                    cp_commit();
                    cp_wait<1>();
                } else {
                    cp_wait<0>();
                }
                __syncthreads();

                const float* buf = abuf + (c & 1) * (64 * AS_STRIDE);
                const float* Abase = buf + (bq * 4) * AS_STRIDE + ks * 4;
                const float* Wbase = ws + (hq * 4) * WS_STRIDE + c * BK + ks * 4;

#pragma unroll
                for (int g = 0; g < 4; ++g) {          // 4 groups of 32 k
                    const int ko = g * 32;
                    ulonglong2 a0 = *(const ulonglong2*)(Abase + 0 * AS_STRIDE + ko);
                    ulonglong2 a1 = *(const ulonglong2*)(Abase + 1 * AS_STRIDE + ko);
                    ulonglong2 a2 = *(const ulonglong2*)(Abase + 2 * AS_STRIDE + ko);
                    ulonglong2 a3 = *(const ulonglong2*)(Abase + 3 * AS_STRIDE + ko);
                    ulonglong2 w0 = *(const ulonglong2*)(Wbase + 0 * WS_STRIDE + ko);
                    ulonglong2 w1 = *(const ulonglong2*)(Wbase + 1 * WS_STRIDE + ko);
                    ulonglong2 w2 = *(const ulonglong2*)(Wbase + 2 * WS_STRIDE + ko);
                    ulonglong2 w3 = *(const ulonglong2*)(Wbase + 3 * WS_STRIDE + ko);

                    ffma2(acc[0][0], a0.x, w0.x); ffma2(acc[0][0], a0.y, w0.y);
                    ffma2(acc[0][1], a0.x, w1.x); ffma2(acc[0][1], a0.y, w1.y);
                    ffma2(acc[0][2], a0.x, w2.x); ffma2(acc[0][2], a0.y, w2.y);
                    ffma2(acc[0][3], a0.x, w3.x); ffma2(acc[0][3], a0.y, w3.y);
                    ffma2(acc[1][0], a1.x, w0.x); ffma2(acc[1][0], a1.y, w0.y);
                    ffma2(acc[1][1], a1.x, w1.x); ffma2(acc[1][1], a1.y, w1.y);
                    ffma2(acc[1][2], a1.x, w2.x); ffma2(acc[1][2], a1.y, w2.y);
                    ffma2(acc[1][3], a1.x, w3.x); ffma2(acc[1][3], a1.y, w3.y);
                    ffma2(acc[2][0], a2.x, w0.x); ffma2(acc[2][0], a2.y, w0.y);
                    ffma2(acc[2][1], a2.x, w1.x); ffma2(acc[2][1], a2.y, w1.y);
                    ffma2(acc[2][2], a2.x, w2.x); ffma2(acc[2][2], a2.y, w2.y);
                    ffma2(acc[2][3], a2.x, w3.x); ffma2(acc[2][3], a2.y, w3.y);
                    ffma2(acc[3][0], a3.x, w0.x); ffma2(acc[3][0], a3.y, w0.y);
                    ffma2(acc[3][1], a3.x, w1.x); ffma2(acc[3][1], a3.y, w1.y);
                    ffma2(acc[3][2], a3.x, w2.x); ffma2(acc[3][2], a3.y, w2.y);
                    ffma2(acc[3][3], a3.x, w3.x); ffma2(acc[3][3], a3.y, w3.y);
                }
                __syncthreads();
            }
        }

        // reduce over 8 ks lanes (lane bits 0..2) and write
        float res[4][4];
#pragma unroll
        for (int bi = 0; bi < 4; ++bi) {
#pragma unroll
            for (int hj = 0; hj < 4; ++hj) {
                float s = f2_lo(acc[bi][hj]) + f2_hi(acc[bi][hj]);
                s += __shfl_xor_sync(0xffffffffu, s, 1);
                s += __shfl_xor_sync(0xffffffffu, s, 2);
                s += __shfl_xor_sync(0xffffffffu, s, 4);
                res[bi][hj] = s;
            }
        }

        if (writer) {
            float* next = g_states + (size_t)t * B_ * H_;
#pragma unroll
            for (int bi = 0; bi < 4; ++bi) {
                const int b = bq * 4 + bi;
                int tk = tok_all[t * B_ + b];
                tk = (tk < 0) ? 0 : ((tk >= V_) ? V_ - 1 : tk);
                float4 v;
                v.x = tanhf(res[bi][0] + bias4.x + wrow0[tk]);
                v.y = tanhf(res[bi][1] + bias4.y + wrow1[tk]);
                v.z = tanhf(res[bi][2] + bias4.z + wrow2[tk]);
                v.w = tanhf(res[bi][3] + bias4.w + wrow3[tk]);
                *(float4*)(next + (size_t)b * H_ + h0 + hq * 4) = v;
            }
        }

        grid_barrier();
    }
}

// ---------------------------------------------------------------------------
// Batched output projection (R2 scalar version, measured-good):
//   out[m, v] = output_b[v] + sum_h S[m,h] * output_w[v,h]
// BM=BN=128, BK=8, 256 threads, 8x8 microtile.
// ---------------------------------------------------------------------------
__global__ void out_gemm_kernel(const float* __restrict__ W,   // [V_][H_]
                                const float* __restrict__ ob,  // [V_]
                                float* __restrict__ out)       // [T_*B_][V_]
{
    __shared__ float As[8][128];  // [k][m]
    __shared__ float Bs[8][128];  // [k][n]

    const float* S = g_states;    // [T_*B_][H_]

    const int tid = threadIdx.x;
    const int m0  = blockIdx.y * 128;
    const int n0  = blockIdx.x * 128;
    const int tx  = tid & 15;
    const int ty  = tid >> 4;
    const int mr  = ty * 8;
    const int nr  = tx * 8;

    float acc[8][8];
#pragma unroll
    for (int i = 0; i < 8; i++)
#pragma unroll
        for (int j = 0; j < 8; j++) acc[i][j] = 0.0f;

    const int lrow = tid >> 1;        // 0..127
    const int lk   = (tid & 1) * 4;   // 0 or 4

    for (int k0 = 0; k0 < H_; k0 += 8) {
        float4 av = *(const float4*)(S + (size_t)(m0 + lrow) * H_ + k0 + lk);
        float4 bv = *(const float4*)(W + (size_t)(n0 + lrow) * H_ + k0 + lk);
        As[lk + 0][lrow] = av.x; As[lk + 1][lrow] = av.y;
        As[lk + 2][lrow] = av.z; As[lk + 3][lrow] = av.w;
        Bs[lk + 0][lrow] = bv.x; Bs[lk + 1][lrow] = bv.y;
        Bs[lk + 2][lrow] = bv.z; Bs[lk + 3][lrow] = bv.w;
        __syncthreads();
#pragma unroll
        for (int kk = 0; kk < 8; kk++) {
            float a[8], b[8];
            *(float4*)&a[0] = *(const float4*)&As[kk][mr];
            *(float4*)&a[4] = *(const float4*)&As[kk][mr + 4];
            *(float4*)&b[0] = *(const float4*)&Bs[kk][nr];
            *(float4*)&b[4] = *(const float4*)&Bs[kk][nr + 4];
#pragma unroll
            for (int i = 0; i < 8; i++)
#pragma unroll
                for (int j = 0; j < 8; j++)
                    acc[i][j] += a[i] * b[j];
        }
        __syncthreads();
    }

#pragma unroll
    for (int i = 0; i < 8; i++) {
        const int m = m0 + mr + i;
#pragma unroll
        for (int j = 0; j < 8; j += 4) {
            const int n = n0 + nr + j;
            float4 o;
            o.x = acc[i][j + 0] + ob[n + 0];
            o.y = acc[i][j + 1] + ob[n + 1];
            o.z = acc[i][j + 2] + ob[n + 2];
            o.w = acc[i][j + 3] + ob[n + 3];
            *(float4*)(out + (size_t)m * V_ + n) = o;
        }
    }
}

// Copy final state (g_states[T_-1]) to the tail of the output buffer.
__global__ void copy_final_state_kernel(float* __restrict__ dst)
{
    const float* src = g_states + (size_t)(T_ - 1) * B_ * H_;
    int idx = blockIdx.x * blockDim.x + threadIdx.x;
    if (idx < B_ * H_) dst[idx] = src[idx];
}

extern "C" void kernel_launch(void* const* d_in, const int* in_sizes, int n_in,
                              void* d_out, int out_size)
{
    const int*   inputs   = (const int*)d_in[0];     // [T_][B_] int32
    const float* hidden_w = (const float*)d_in[1];   // [H_][VH_]
    const float* hidden_b = (const float*)d_in[2];   // [H_]
    const float* output_w = (const float*)d_in[3];   // [V_][H_]
    const float* output_b = (const float*)d_in[4];   // [V_]
    float*       out      = (float*)d_out;

    (void)in_sizes; (void)n_in;

    const int smem_bytes = (HW * WS_STRIDE + 2 * 64 * AS_STRIDE) * sizeof(float);
    cudaFuncSetAttribute(rnn_persistent,
                         cudaFuncAttributeMaxDynamicSharedMemorySize, smem_bytes);

    // One persistent launch runs all 128 recurrence steps.
    rnn_persistent<<<NCTA, TPB, smem_bytes>>>(inputs, hidden_w, hidden_b);

    // Batched output projection over all timesteps
    dim3 grid(V_ / 128, (T_ * B_) / 128);
    out_gemm_kernel<<<grid, 256>>>(output_w, output_b, out);

    // Final state, if the output buffer includes it (outputs first, then final_state)
    const size_t outputs_elems = (size_t)T_ * B_ * V_;
    if ((size_t)out_size >= outputs_elems + (size_t)B_ * H_) {
        copy_final_state_kernel<<<(B_ * H_ + 255) / 256, 256>>>(out + outputs_elems);
    }
}

// round 13
// speedup vs baseline: 1.1197x; 1.1197x over previous
#include <cuda_runtime.h>
#include <cuda_bf16.h>
#include <math.h>

// Problem dims
#define T_  128
#define B_  64
#define V_  8192
#define H_  2048
#define VH_ 10240   // V_ + H_

#define NCTA 128          // persistent CTAs, one per SM (h-slice of 16)
#define TPB  256
#define HW   16           // h rows per CTA
#define BK   64           // k chunk (bf16) staged per double-buffer slot
#define WSTR 2056         // W smem row stride in bf16 elems (2048 + 8)
#define ASTR 72           // A chunk smem row stride in bf16 elems (64 + 8)

// State history fp32: g_states[t][b][h]  (64 MB device-global scratch)
__device__ __align__(16) float g_states[(size_t)T_ * B_ * H_];
// bf16 split state ring (2 deep): hi and lo parts, [buf][b][h]
__device__ __align__(16) __nv_bfloat16 g_shi[2][B_ * H_];
__device__ __align__(16) __nv_bfloat16 g_slo[2][B_ * H_];

// Grid barrier state (zero-initialized)
__device__ unsigned g_bar_gen;
__device__ unsigned g_bar_cnt;

// ---------------------------------------------------------------------------
// helpers
// ---------------------------------------------------------------------------
__device__ __forceinline__ void cp_async16(void* sdst, const void* gsrc)
{
    unsigned sa = (unsigned)__cvta_generic_to_shared(sdst);
    asm volatile("cp.async.cg.shared.global [%0], [%1], 16;\n" :: "r"(sa), "l"(gsrc));
}
__device__ __forceinline__ void cp_commit()
{ asm volatile("cp.async.commit_group;\n"); }
template<int N> __device__ __forceinline__ void cp_wait()
{ asm volatile("cp.async.wait_group %0;\n" :: "n"(N)); }

__device__ __forceinline__ void mma_bf16_16816(float& c0, float& c1, float& c2, float& c3,
                                               unsigned a0, unsigned a1, unsigned a2, unsigned a3,
                                               unsigned b0, unsigned b1)
{
    asm volatile(
        "mma.sync.aligned.m16n8k16.row.col.f32.bf16.bf16.f32 "
        "{%0,%1,%2,%3}, {%4,%5,%6,%7}, {%8,%9}, {%0,%1,%2,%3};"
        : "+f"(c0), "+f"(c1), "+f"(c2), "+f"(c3)
        : "r"(a0), "r"(a1), "r"(a2), "r"(a3), "r"(b0), "r"(b1));
}

__device__ __forceinline__ void grid_barrier()
{
    __syncthreads();
    if (threadIdx.x == 0) {
        __threadfence();
        unsigned gen = *(volatile unsigned*)&g_bar_gen;
        unsigned t = atomicAdd(&g_bar_cnt, 1u);
        if (t == NCTA - 1) {
            atomicExch(&g_bar_cnt, 0u);
            __threadfence();
            atomicAdd(&g_bar_gen, 1u);
        } else {
            while (*(volatile unsigned*)&g_bar_gen == gen) { }
        }
        __threadfence();
    }
    __syncthreads();
}

// ---------------------------------------------------------------------------
// Persistent recurrence kernel, v4: tensor cores (mma.sync bf16) with
// hi/lo split precision.  grid = 128 CTAs x 256 threads.
// CTA owns h rows [bid*16, bid*16+16).  Per step each of 8 warps computes one
// m16(b) x n8(h) tile of  state_prev @ W_hh^T  via 3-pass bf16 split:
//     acc += hi@Whi + hi@Wlo + lo@Whi      (lo@Wlo dropped, ~2^-16 rel)
// ---------------------------------------------------------------------------
extern __shared__ char s_raw[];

__global__ __launch_bounds__(TPB, 1)
void rnn_persistent(const int* __restrict__ tok_all,     // [T_][B_]
                    const float* __restrict__ hidden_w,  // [H_][VH_]
                    const float* __restrict__ hidden_b)  // [H_]
{
    __nv_bfloat16* Whi = (__nv_bfloat16*)s_raw;                  // [16][WSTR]
    __nv_bfloat16* Wlo = Whi + HW * WSTR;                        // [16][WSTR]
    __nv_bfloat16* Abuf = Wlo + HW * WSTR;  // [2 buf][2 arr(hi,lo)][64][ASTR]
    const int ABSZ = 64 * ASTR;             // one array

    const int tid  = threadIdx.x;
    const int lane = tid & 31;
    const int wid  = tid >> 5;
    const int h0   = blockIdx.x * HW;

    // --- prologue: split W_hh slice into bf16 hi/lo in SMEM (once) ---
    for (int idx = tid; idx < HW * H_; idx += TPB) {
        int r = idx >> 11;          // /2048
        int k = idx & (H_ - 1);
        float w = hidden_w[(size_t)(h0 + r) * VH_ + V_ + k];
        __nv_bfloat16 hi = __float2bfloat16(w);
        float rem = w - __bfloat162float(hi);
        Whi[r * WSTR + k] = hi;
        Wlo[r * WSTR + k] = __float2bfloat16(rem);
    }
    __syncthreads();

    // warp tile: m_off (b), n_off (h within slice)
    const int m_off = 16 * (wid & 3);
    const int n_off = 8 * (wid >> 2);
    const int g  = lane >> 2;         // 0..7
    const int kk = (lane & 3) * 2;    // 0,2,4,6

    // epilogue constants (fixed h, b indices per lane)
    const int hI  = h0 + n_off + kk;      // h pair (hI, hI+1)
    const int bI0 = m_off + g;            // b rows bI0, bI0+8
    const float bias0 = hidden_b[hI];
    const float bias1 = hidden_b[hI + 1];
    const float* wr0 = hidden_w + (size_t)hI * VH_;
    const float* wr1 = hidden_w + (size_t)(hI + 1) * VH_;

    // staging mapping: 64 rows x 8 units(16B) per array, 2 rows per thread
    const int st_r = tid >> 3;            // 0..31 (rows st_r, st_r+32)
    const int st_u = (tid & 7) * 8;       // bf16 col offset 0..56

    for (int t = 0; t < T_; ++t) {
        float c0 = 0.f, c1 = 0.f, c2 = 0.f, c3 = 0.f;
        const int cur = t & 1, pb = cur ^ 1;

        if (t > 0) {
            const __nv_bfloat16* ph = g_shi[pb];
            const __nv_bfloat16* pl = g_slo[pb];

            // prefetch chunk 0 into buffer 0
            {
                __nv_bfloat16* Ah = Abuf;           // buf0 hi
                __nv_bfloat16* Al = Abuf + ABSZ;    // buf0 lo
#pragma unroll
                for (int i = 0; i < 2; ++i) {
                    int r = st_r + 32 * i;
                    cp_async16(Ah + r * ASTR + st_u, ph + (size_t)r * H_ + st_u);
                    cp_async16(Al + r * ASTR + st_u, pl + (size_t)r * H_ + st_u);
                }
                cp_commit();
            }

            const int NCH = H_ / BK;   // 32
            for (int c = 0; c < NCH; ++c) {
                if (c + 1 < NCH) {
                    __nv_bfloat16* Ah = Abuf + ((c + 1) & 1) * 2 * ABSZ;
                    __nv_bfloat16* Al = Ah + ABSZ;
                    const int k0 = (c + 1) * BK;
#pragma unroll
                    for (int i = 0; i < 2; ++i) {
                        int r = st_r + 32 * i;
                        cp_async16(Ah + r * ASTR + st_u, ph + (size_t)r * H_ + k0 + st_u);
                        cp_async16(Al + r * ASTR + st_u, pl + (size_t)r * H_ + k0 + st_u);
                    }
                    cp_commit();
                    cp_wait<1>();
                } else {
                    cp_wait<0>();
                }
                __syncthreads();

                const __nv_bfloat16* Ah = Abuf + (c & 1) * 2 * ABSZ;
                const __nv_bfloat16* Al = Ah + ABSZ;

#pragma unroll
                for (int ksx = 0; ksx < BK / 16; ++ksx) {   // 4 k16 steps
                    const int ko = ksx * 16;
                    // A fragments (hi and lo)
                    const __nv_bfloat16* pah = Ah + (m_off + g) * ASTR + ko + kk;
                    const __nv_bfloat16* pal = Al + (m_off + g) * ASTR + ko + kk;
                    unsigned ah0 = *(const unsigned*)(pah);
                    unsigned ah1 = *(const unsigned*)(pah + 8 * ASTR);
                    unsigned ah2 = *(const unsigned*)(pah + 8);
                    unsigned ah3 = *(const unsigned*)(pah + 8 * ASTR + 8);
                    unsigned al0 = *(const unsigned*)(pal);
                    unsigned al1 = *(const unsigned*)(pal + 8 * ASTR);
                    unsigned al2 = *(const unsigned*)(pal + 8);
                    unsigned al3 = *(const unsigned*)(pal + 8 * ASTR + 8);
                    // B fragments from W slices (col-major k x n == W[n][k])
                    const int kglob = c * BK + ko;
                    const __nv_bfloat16* pbh = Whi + (n_off + g) * WSTR + kglob + kk;
                    const __nv_bfloat16* pbl = Wlo + (n_off + g) * WSTR + kglob + kk;
                    unsigned bh0 = *(const unsigned*)(pbh);
                    unsigned bh1 = *(const unsigned*)(pbh + 8);
                    unsigned bl0 = *(const unsigned*)(pbl);
                    unsigned bl1 = *(const unsigned*)(pbl + 8);

                    mma_bf16_16816(c0, c1, c2, c3, ah0, ah1, ah2, ah3, bh0, bh1);
                    mma_bf16_16816(c0, c1, c2, c3, ah0, ah1, ah2, ah3, bl0, bl1);
                    mma_bf16_16816(c0, c1, c2, c3, al0, al1, al2, al3, bh0, bh1);
                }
                __syncthreads();
            }
        }

        // --- epilogue: bias + one-hot embedding + tanh; write fp32 + bf16 split ---
        {
            float* next = g_states + (size_t)t * B_ * H_;
            __nv_bfloat16* shi = g_shi[cur];
            __nv_bfloat16* slo = g_slo[cur];

#pragma unroll
            for (int half = 0; half < 2; ++half) {
                const int b = bI0 + 8 * half;
                const float x0 = half ? c2 : c0;
                const float x1 = half ? c3 : c1;
                int tk = tok_all[t * B_ + b];
                tk = (tk < 0) ? 0 : ((tk >= V_) ? V_ - 1 : tk);
                float v0 = tanhf(x0 + bias0 + wr0[tk]);
                float v1 = tanhf(x1 + bias1 + wr1[tk]);

                *(float2*)(next + (size_t)b * H_ + hI) = make_float2(v0, v1);

                __nv_bfloat16 h0b = __float2bfloat16(v0);
                __nv_bfloat16 h1b = __float2bfloat16(v1);
                __nv_bfloat162 hh; hh.x = h0b; hh.y = h1b;
                *(__nv_bfloat162*)(shi + (size_t)b * H_ + hI) = hh;
                __nv_bfloat162 ll;
                ll.x = __float2bfloat16(v0 - __bfloat162float(h0b));
                ll.y = __float2bfloat16(v1 - __bfloat162float(h1b));
                *(__nv_bfloat162*)(slo + (size_t)b * H_ + hI) = ll;
            }
        }

        grid_barrier();
    }
}

// ---------------------------------------------------------------------------
// Batched output projection (scalar fp32, measured-good ~2.9 ms):
//   out[m, v] = output_b[v] + sum_h S[m,h] * output_w[v,h]
// BM=BN=128, BK=8, 256 threads, 8x8 microtile.
// ---------------------------------------------------------------------------
__global__ void out_gemm_kernel(const float* __restrict__ W,   // [V_][H_]
                                const float* __restrict__ ob,  // [V_]
                                float* __restrict__ out)       // [T_*B_][V_]
{
    __shared__ float As[8][128];  // [k][m]
    __shared__ float Bs[8][128];  // [k][n]

    const float* S = g_states;    // [T_*B_][H_]

    const int tid = threadIdx.x;
    const int m0  = blockIdx.y * 128;
    const int n0  = blockIdx.x * 128;
    const int tx  = tid & 15;
    const int ty  = tid >> 4;
    const int mr  = ty * 8;
    const int nr  = tx * 8;

    float acc[8][8];
#pragma unroll
    for (int i = 0; i < 8; i++)
#pragma unroll
        for (int j = 0; j < 8; j++) acc[i][j] = 0.0f;

    const int lrow = tid >> 1;        // 0..127
    const int lk   = (tid & 1) * 4;   // 0 or 4

    for (int k0 = 0; k0 < H_; k0 += 8) {
        float4 av = *(const float4*)(S + (size_t)(m0 + lrow) * H_ + k0 + lk);
        float4 bv = *(const float4*)(W + (size_t)(n0 + lrow) * H_ + k0 + lk);
        As[lk + 0][lrow] = av.x; As[lk + 1][lrow] = av.y;
        As[lk + 2][lrow] = av.z; As[lk + 3][lrow] = av.w;
        Bs[lk + 0][lrow] = bv.x; Bs[lk + 1][lrow] = bv.y;
        Bs[lk + 2][lrow] = bv.z; Bs[lk + 3][lrow] = bv.w;
        __syncthreads();
#pragma unroll
        for (int kk = 0; kk < 8; kk++) {
            float a[8], b[8];
            *(float4*)&a[0] = *(const float4*)&As[kk][mr];
            *(float4*)&a[4] = *(const float4*)&As[kk][mr + 4];
            *(float4*)&b[0] = *(const float4*)&Bs[kk][nr];
            *(float4*)&b[4] = *(const float4*)&Bs[kk][nr + 4];
#pragma unroll
            for (int i = 0; i < 8; i++)
#pragma unroll
                for (int j = 0; j < 8; j++)
                    acc[i][j] += a[i] * b[j];
        }
        __syncthreads();
    }

#pragma unroll
    for (int i = 0; i < 8; i++) {
        const int m = m0 + mr + i;
#pragma unroll
        for (int j = 0; j < 8; j += 4) {
            const int n = n0 + nr + j;
            float4 o;
            o.x = acc[i][j + 0] + ob[n + 0];
            o.y = acc[i][j + 1] + ob[n + 1];
            o.z = acc[i][j + 2] + ob[n + 2];
            o.w = acc[i][j + 3] + ob[n + 3];
            *(float4*)(out + (size_t)m * V_ + n) = o;
        }
    }
}

// Copy final state (g_states[T_-1]) to the tail of the output buffer.
__global__ void copy_final_state_kernel(float* __restrict__ dst)
{
    const float* src = g_states + (size_t)(T_ - 1) * B_ * H_;
    int idx = blockIdx.x * blockDim.x + threadIdx.x;
    if (idx < B_ * H_) dst[idx] = src[idx];
}

extern "C" void kernel_launch(void* const* d_in, const int* in_sizes, int n_in,
                              void* d_out, int out_size)
{
    const int*   inputs   = (const int*)d_in[0];     // [T_][B_] int32
    const float* hidden_w = (const float*)d_in[1];   // [H_][VH_]
    const float* hidden_b = (const float*)d_in[2];   // [H_]
    const float* output_w = (const float*)d_in[3];   // [V_][H_]
    const float* output_b = (const float*)d_in[4];   // [V_]
    float*       out      = (float*)d_out;

    (void)in_sizes; (void)n_in;

    const int smem_bytes = (2 * HW * WSTR + 2 * 2 * 64 * ASTR) * (int)sizeof(__nv_bfloat16);
    cudaFuncSetAttribute(rnn_persistent,
                         cudaFuncAttributeMaxDynamicSharedMemorySize, smem_bytes);

    // One persistent launch runs all 128 recurrence steps.
    rnn_persistent<<<NCTA, TPB, smem_bytes>>>(inputs, hidden_w, hidden_b);

    // Batched output projection over all timesteps
    dim3 grid(V_ / 128, (T_ * B_) / 128);
    out_gemm_kernel<<<grid, 256>>>(output_w, output_b, out);

    // Final state, if the output buffer includes it (outputs first, then final_state)
    const size_t outputs_elems = (size_t)T_ * B_ * V_;
    if ((size_t)out_size >= outputs_elems + (size_t)B_ * H_) {
        copy_final_state_kernel<<<(B_ * H_ + 255) / 256, 256>>>(out + outputs_elems);
    }
}

// round 14
// speedup vs baseline: 1.1741x; 1.0486x over previous
#include <cuda_runtime.h>
#include <cuda_bf16.h>
#include <math.h>

// Problem dims
#define T_  128
#define B_  64
#define V_  8192
#define H_  2048
#define VH_ 10240   // V_ + H_

#define NCTA 128          // persistent CTAs, one per SM (h-slice of 16)
#define TPB  512          // 16 warps: 8 tiles x 2 k-groups
#define HW   16           // h rows per CTA
#define BK   64           // k chunk (bf16) per group per double-buffer slot
#define NCHG 16           // chunks per k-group (1024 / 64)
#define WSTR 2056         // W smem row stride in bf16 elems (2048 + 8)
#define ASTR 72           // A chunk smem row stride in bf16 elems (64 + 8)

// State history fp32: g_states[t][b][h]  (64 MB device-global scratch)
__device__ __align__(16) float g_states[(size_t)T_ * B_ * H_];
// bf16 split state ring (2 deep): hi and lo parts, [buf][b][h]
__device__ __align__(16) __nv_bfloat16 g_shi[2][B_ * H_];
__device__ __align__(16) __nv_bfloat16 g_slo[2][B_ * H_];

// Grid barrier state (zero-initialized)
__device__ unsigned g_bar_gen;
__device__ unsigned g_bar_cnt;

// ---------------------------------------------------------------------------
// helpers
// ---------------------------------------------------------------------------
__device__ __forceinline__ void cp_async16(void* sdst, const void* gsrc)
{
    unsigned sa = (unsigned)__cvta_generic_to_shared(sdst);
    asm volatile("cp.async.cg.shared.global [%0], [%1], 16;\n" :: "r"(sa), "l"(gsrc));
}
__device__ __forceinline__ void cp_commit()
{ asm volatile("cp.async.commit_group;\n"); }
template<int N> __device__ __forceinline__ void cp_wait()
{ asm volatile("cp.async.wait_group %0;\n" :: "n"(N)); }

__device__ __forceinline__ void ldsm_x4(unsigned& r0, unsigned& r1,
                                        unsigned& r2, unsigned& r3, const void* p)
{
    unsigned a = (unsigned)__cvta_generic_to_shared(p);
    asm volatile("ldmatrix.sync.aligned.m8n8.x4.shared.b16 {%0,%1,%2,%3}, [%4];"
        : "=r"(r0), "=r"(r1), "=r"(r2), "=r"(r3) : "r"(a));
}
__device__ __forceinline__ void ldsm_x2(unsigned& r0, unsigned& r1, const void* p)
{
    unsigned a = (unsigned)__cvta_generic_to_shared(p);
    asm volatile("ldmatrix.sync.aligned.m8n8.x2.shared.b16 {%0,%1}, [%2];"
        : "=r"(r0), "=r"(r1) : "r"(a));
}

__device__ __forceinline__ void mma_bf16_16816(float& c0, float& c1, float& c2, float& c3,
                                               unsigned a0, unsigned a1, unsigned a2, unsigned a3,
                                               unsigned b0, unsigned b1)
{
    asm volatile(
        "mma.sync.aligned.m16n8k16.row.col.f32.bf16.bf16.f32 "
        "{%0,%1,%2,%3}, {%4,%5,%6,%7}, {%8,%9}, {%0,%1,%2,%3};"
        : "+f"(c0), "+f"(c1), "+f"(c2), "+f"(c3)
        : "r"(a0), "r"(a1), "r"(a2), "r"(a3), "r"(b0), "r"(b1));
}

__device__ __forceinline__ void grid_barrier()
{
    __syncthreads();
    if (threadIdx.x == 0) {
        __threadfence();
        unsigned gen = *(volatile unsigned*)&g_bar_gen;
        unsigned t = atomicAdd(&g_bar_cnt, 1u);
        if (t == NCTA - 1) {
            atomicExch(&g_bar_cnt, 0u);
            __threadfence();
            atomicAdd(&g_bar_gen, 1u);
        } else {
            while (*(volatile unsigned*)&g_bar_gen == gen) { }
        }
        __threadfence();
    }
    __syncthreads();
}

// ---------------------------------------------------------------------------
// Persistent recurrence kernel, v5: mma.sync bf16 hi/lo split (3-pass),
// ldmatrix fragment loads, 16 warps with 2-way k-split + SMEM reduction.
// grid = 128 CTAs x 512 threads. CTA owns h rows [bid*16, bid*16+16).
// Warp w: tile = w&7 (m_off=16*(tile&3) b, n_off=8*(tile>>2) h),
//         k-group = w>>3 (k in [grp*1024, grp*1024+1024)).
// ---------------------------------------------------------------------------
extern __shared__ char s_raw[];

__global__ __launch_bounds__(TPB, 1)
void rnn_persistent(const int* __restrict__ tok_all,     // [T_][B_]
                    const float* __restrict__ hidden_w,  // [H_][VH_]
                    const float* __restrict__ hidden_b)  // [H_]
{
    __nv_bfloat16* Whi  = (__nv_bfloat16*)s_raw;          // [16][WSTR]
    __nv_bfloat16* Wlo  = Whi + HW * WSTR;                // [16][WSTR]
    __nv_bfloat16* Abuf = Wlo + HW * WSTR;                // [2grp][2buf][2arr][64][ASTR]
    const int AARR = 64 * ASTR;                           // one array, elems
    float4* sred = (float4*)(Abuf + 2 * 2 * 2 * AARR);    // [8 tiles][32 lanes]

    const int tid  = threadIdx.x;
    const int lane = tid & 31;
    const int wid  = tid >> 5;
    const int h0   = blockIdx.x * HW;

    // --- prologue: split W_hh slice into bf16 hi/lo in SMEM (once) ---
    for (int idx = tid; idx < HW * H_; idx += TPB) {
        int r = idx >> 11;          // /2048
        int k = idx & (H_ - 1);
        float w = hidden_w[(size_t)(h0 + r) * VH_ + V_ + k];
        __nv_bfloat16 hi = __float2bfloat16(w);
        float rem = w - __bfloat162float(hi);
        Whi[r * WSTR + k] = hi;
        Wlo[r * WSTR + k] = __float2bfloat16(rem);
    }
    __syncthreads();

    // warp mapping
    const int tile  = wid & 7;
    const int grp   = wid >> 3;
    const int m_off = 16 * (tile & 3);
    const int n_off = 8 * (tile >> 2);
    const int g  = lane >> 2;         // 0..7
    const int kk = (lane & 3) * 2;    // 0,2,4,6

    // ldmatrix lane-address offsets (in bf16 elems, relative to tile base)
    const int aOff = (m_off + (lane & 15)) * ASTR + ((lane >> 4) << 3);
    const int bOff = (n_off + (lane & 7)) * WSTR + (((lane >> 3) & 1) << 3);

    // epilogue constants (used by grp 0 warps)
    const int hI  = h0 + n_off + kk;      // h pair (hI, hI+1)
    const int bI0 = m_off + g;            // b rows bI0, bI0+8
    const float bias0 = hidden_b[hI];
    const float bias1 = hidden_b[hI + 1];
    const float* wr0 = hidden_w + (size_t)hI * VH_;
    const float* wr1 = hidden_w + (size_t)(hI + 1) * VH_;

    // staging mapping: 512 threads cover 64 rows x 8 units(16B); each thread
    // stages 4 arrays (2 groups x hi/lo) at (st_r, st_u)
    const int st_r = tid >> 3;            // 0..63
    const int st_u = (tid & 7) * 8;       // bf16 col offset 0..56

    for (int t = 0; t < T_; ++t) {
        float c0 = 0.f, c1 = 0.f, c2 = 0.f, c3 = 0.f;
        const int cur = t & 1, pb = cur ^ 1;

        if (t > 0) {
            const __nv_bfloat16* ph = g_shi[pb];
            const __nv_bfloat16* pl = g_slo[pb];

            // prefetch chunk 0 (both groups) into buffer 0
            {
#pragma unroll
                for (int g2 = 0; g2 < 2; ++g2) {
                    const int k0 = g2 * 1024;
                    __nv_bfloat16* Ah = Abuf + (g2 * 2 + 0) * 2 * AARR; // grp g2, buf0, hi
                    __nv_bfloat16* Al = Ah + AARR;
                    cp_async16(Ah + st_r * ASTR + st_u, ph + (size_t)st_r * H_ + k0 + st_u);
                    cp_async16(Al + st_r * ASTR + st_u, pl + (size_t)st_r * H_ + k0 + st_u);
                }
                cp_commit();
            }

            for (int c = 0; c < NCHG; ++c) {
                if (c + 1 < NCHG) {
                    const int buf = (c + 1) & 1;
#pragma unroll
                    for (int g2 = 0; g2 < 2; ++g2) {
                        const int k0 = g2 * 1024 + (c + 1) * BK;
                        __nv_bfloat16* Ah = Abuf + (g2 * 2 + buf) * 2 * AARR;
                        __nv_bfloat16* Al = Ah + AARR;
                        cp_async16(Ah + st_r * ASTR + st_u, ph + (size_t)st_r * H_ + k0 + st_u);
                        cp_async16(Al + st_r * ASTR + st_u, pl + (size_t)st_r * H_ + k0 + st_u);
                    }
                    cp_commit();
                    cp_wait<1>();
                } else {
                    cp_wait<0>();
                }
                __syncthreads();

                const __nv_bfloat16* Ah = Abuf + (grp * 2 + (c & 1)) * 2 * AARR;
                const __nv_bfloat16* Al = Ah + AARR;
                const int kbase = grp * 1024 + c * BK;

#pragma unroll
                for (int ksx = 0; ksx < BK / 16; ++ksx) {   // 4 k16 steps
                    const int ko = ksx * 16;
                    unsigned ah0, ah1, ah2, ah3, al0, al1, al2, al3;
                    unsigned bh0, bh1, bl0, bl1;
                    ldsm_x4(ah0, ah1, ah2, ah3, Ah + aOff + ko);
                    ldsm_x4(al0, al1, al2, al3, Al + aOff + ko);
                    ldsm_x2(bh0, bh1, Whi + bOff + kbase + ko);
                    ldsm_x2(bl0, bl1, Wlo + bOff + kbase + ko);

                    mma_bf16_16816(c0, c1, c2, c3, ah0, ah1, ah2, ah3, bh0, bh1);
                    mma_bf16_16816(c0, c1, c2, c3, ah0, ah1, ah2, ah3, bl0, bl1);
                    mma_bf16_16816(c0, c1, c2, c3, al0, al1, al2, al3, bh0, bh1);
                }
                __syncthreads();
            }
        }

        // --- k-split reduction: group 1 stores partials, group 0 accumulates ---
        if (grp == 1) sred[tile * 32 + lane] = make_float4(c0, c1, c2, c3);
        __syncthreads();

        if (grp == 0) {
            float4 o = sred[tile * 32 + lane];
            c0 += o.x; c1 += o.y; c2 += o.z; c3 += o.w;

            float* next = g_states + (size_t)t * B_ * H_;
            __nv_bfloat16* shi = g_shi[cur];
            __nv_bfloat16* slo = g_slo[cur];

#pragma unroll
            for (int half = 0; half < 2; ++half) {
                const int b = bI0 + 8 * half;
                const float x0 = half ? c2 : c0;
                const float x1 = half ? c3 : c1;
                int tk = tok_all[t * B_ + b];
                tk = (tk < 0) ? 0 : ((tk >= V_) ? V_ - 1 : tk);
                float v0 = tanhf(x0 + bias0 + wr0[tk]);
                float v1 = tanhf(x1 + bias1 + wr1[tk]);

                *(float2*)(next + (size_t)b * H_ + hI) = make_float2(v0, v1);

                __nv_bfloat16 h0b = __float2bfloat16(v0);
                __nv_bfloat16 h1b = __float2bfloat16(v1);
                __nv_bfloat162 hh; hh.x = h0b; hh.y = h1b;
                *(__nv_bfloat162*)(shi + (size_t)b * H_ + hI) = hh;
                __nv_bfloat162 ll;
                ll.x = __float2bfloat16(v0 - __bfloat162float(h0b));
                ll.y = __float2bfloat16(v1 - __bfloat162float(h1b));
                *(__nv_bfloat162*)(slo + (size_t)b * H_ + hI) = ll;
            }
        }

        grid_barrier();
    }
}

// ---------------------------------------------------------------------------
// Batched output projection (scalar fp32, measured-good ~2.9 ms):
//   out[m, v] = output_b[v] + sum_h S[m,h] * output_w[v,h]
// BM=BN=128, BK=8, 256 threads, 8x8 microtile.
// ---------------------------------------------------------------------------
__global__ void out_gemm_kernel(const float* __restrict__ W,   // [V_][H_]
                                const float* __restrict__ ob,  // [V_]
                                float* __restrict__ out)       // [T_*B_][V_]
{
    __shared__ float As[8][128];  // [k][m]
    __shared__ float Bs[8][128];  // [k][n]

    const float* S = g_states;    // [T_*B_][H_]

    const int tid = threadIdx.x;
    const int m0  = blockIdx.y * 128;
    const int n0  = blockIdx.x * 128;
    const int tx  = tid & 15;
    const int ty  = tid >> 4;
    const int mr  = ty * 8;
    const int nr  = tx * 8;

    float acc[8][8];
#pragma unroll
    for (int i = 0; i < 8; i++)
#pragma unroll
        for (int j = 0; j < 8; j++) acc[i][j] = 0.0f;

    const int lrow = tid >> 1;        // 0..127
    const int lk   = (tid & 1) * 4;   // 0 or 4

    for (int k0 = 0; k0 < H_; k0 += 8) {
        float4 av = *(const float4*)(S + (size_t)(m0 + lrow) * H_ + k0 + lk);
        float4 bv = *(const float4*)(W + (size_t)(n0 + lrow) * H_ + k0 + lk);
        As[lk + 0][lrow] = av.x; As[lk + 1][lrow] = av.y;
        As[lk + 2][lrow] = av.z; As[lk + 3][lrow] = av.w;
        Bs[lk + 0][lrow] = bv.x; Bs[lk + 1][lrow] = bv.y;
        Bs[lk + 2][lrow] = bv.z; Bs[lk + 3][lrow] = bv.w;
        __syncthreads();
#pragma unroll
        for (int kk = 0; kk < 8; kk++) {
            float a[8], b[8];
            *(float4*)&a[0] = *(const float4*)&As[kk][mr];
            *(float4*)&a[4] = *(const float4*)&As[kk][mr + 4];
            *(float4*)&b[0] = *(const float4*)&Bs[kk][nr];
            *(float4*)&b[4] = *(const float4*)&Bs[kk][nr + 4];
#pragma unroll
            for (int i = 0; i < 8; i++)
#pragma unroll
                for (int j = 0; j < 8; j++)
                    acc[i][j] += a[i] * b[j];
        }
        __syncthreads();
    }

#pragma unroll
    for (int i = 0; i < 8; i++) {
        const int m = m0 + mr + i;
#pragma unroll
        for (int j = 0; j < 8; j += 4) {
            const int n = n0 + nr + j;
            float4 o;
            o.x = acc[i][j + 0] + ob[n + 0];
            o.y = acc[i][j + 1] + ob[n + 1];
            o.z = acc[i][j + 2] + ob[n + 2];
            o.w = acc[i][j + 3] + ob[n + 3];
            *(float4*)(out + (size_t)m * V_ + n) = o;
        }
    }
}

// Copy final state (g_states[T_-1]) to the tail of the output buffer.
__global__ void copy_final_state_kernel(float* __restrict__ dst)
{
    const float* src = g_states + (size_t)(T_ - 1) * B_ * H_;
    int idx = blockIdx.x * blockDim.x + threadIdx.x;
    if (idx < B_ * H_) dst[idx] = src[idx];
}

extern "C" void kernel_launch(void* const* d_in, const int* in_sizes, int n_in,
                              void* d_out, int out_size)
{
    const int*   inputs   = (const int*)d_in[0];     // [T_][B_] int32
    const float* hidden_w = (const float*)d_in[1];   // [H_][VH_]
    const float* hidden_b = (const float*)d_in[2];   // [H_]
    const float* output_w = (const float*)d_in[3];   // [V_][H_]
    const float* output_b = (const float*)d_in[4];   // [V_]
    float*       out      = (float*)d_out;

    (void)in_sizes; (void)n_in;

    // Whi+Wlo + A buffers + reduction scratch
    const int smem_bytes = (2 * HW * WSTR + 2 * 2 * 2 * 64 * ASTR) * (int)sizeof(__nv_bfloat16)
                         + 8 * 32 * (int)sizeof(float4);
    cudaFuncSetAttribute(rnn_persistent,
                         cudaFuncAttributeMaxDynamicSharedMemorySize, smem_bytes);

    // One persistent launch runs all 128 recurrence steps.
    rnn_persistent<<<NCTA, TPB, smem_bytes>>>(inputs, hidden_w, hidden_b);

    // Batched output projection over all timesteps
    dim3 grid(V_ / 128, (T_ * B_) / 128);
    out_gemm_kernel<<<grid, 256>>>(output_w, output_b, out);

    // Final state, if the output buffer includes it (outputs first, then final_state)
    const size_t outputs_elems = (size_t)T_ * B_ * V_;
    if ((size_t)out_size >= outputs_elems + (size_t)B_ * H_) {
        copy_final_state_kernel<<<(B_ * H_ + 255) / 256, 256>>>(out + outputs_elems);
    }
}

// round 16
// speedup vs baseline: 1.2294x; 1.0471x over previous
#include <cuda_runtime.h>
#include <cuda_bf16.h>
#include <math.h>

// Problem dims
#define T_  128
#define B_  64
#define V_  8192
#define H_  2048
#define VH_ 10240   // V_ + H_

#define NCTA 128          // persistent CTAs, one per SM (h-slice of 16)
#define TPB  512          // 16 warps: 8 tiles x 2 k-groups
#define HW   16           // h rows per CTA
#define BK   64           // k per chunk
#define NCHG 16           // chunks per k-group (1024 / 64)
#define WSTR 2056         // W smem row stride in bf16 elems (2048 + 8)
#define CHBLK 4096        // elems per 8KB chunk block (64 b x 64 k)

// State history fp32: g_states[t][b][h]  (64 MB device-global scratch)
__device__ __align__(16) float g_states[(size_t)T_ * B_ * H_];
// bf16 split state ring, chunk-contiguous + SW128-swizzled blocks:
// g_ring[buf][chunk=h/64][hi=0/lo=1][ swizzled(b*128 + (h%64)*2) ]
__device__ __align__(128) __nv_bfloat16 g_ring[2][32][2][CHBLK];

// Grid barrier state (zero-initialized)
__device__ unsigned g_bar_gen;
__device__ unsigned g_bar_cnt;

// ---------------------------------------------------------------------------
// helpers
// ---------------------------------------------------------------------------
__device__ __forceinline__ unsigned smem_u32(const void* p)
{ return (unsigned)__cvta_generic_to_shared(p); }

__device__ __forceinline__ unsigned sw128(unsigned o)
{ return o ^ ((o >> 3) & 0x70u); }

__device__ __forceinline__ void mbar_init(unsigned mbar, unsigned cnt)
{ asm volatile("mbarrier.init.shared.b64 [%0], %1;" :: "r"(mbar), "r"(cnt) : "memory"); }

__device__ __forceinline__ void mbar_expect_tx(unsigned mbar, unsigned bytes)
{ asm volatile("mbarrier.arrive.expect_tx.shared.b64 _, [%0], %1;" :: "r"(mbar), "r"(bytes) : "memory"); }

__device__ __forceinline__ void mbar_wait(unsigned mbar, unsigned phase)
{
    asm volatile(
        "{\n\t.reg .pred P;\n"
        "W%=:\n\tmbarrier.try_wait.parity.shared.b64 P, [%0], %1;\n"
        "\t@P bra D%=;\n\tbra W%=;\nD%=:\n\t}"
        :: "r"(mbar), "r"(phase) : "memory");
}

__device__ __forceinline__ void bulk_g2s(unsigned dst_smem, const void* src, unsigned bytes, unsigned mbar)
{
    asm volatile(
        "cp.async.bulk.shared::cta.global.mbarrier::complete_tx::bytes [%0], [%1], %2, [%3];"
        :: "r"(dst_smem), "l"(src), "r"(bytes), "r"(mbar) : "memory");
}

__device__ __forceinline__ void ldsm_x4(unsigned& r0, unsigned& r1,
                                        unsigned& r2, unsigned& r3, unsigned a)
{
    asm volatile("ldmatrix.sync.aligned.m8n8.x4.shared.b16 {%0,%1,%2,%3}, [%4];"
        : "=r"(r0), "=r"(r1), "=r"(r2), "=r"(r3) : "r"(a));
}
__device__ __forceinline__ void ldsm_x2(unsigned& r0, unsigned& r1, const void* p)
{
    unsigned a = smem_u32(p);
    asm volatile("ldmatrix.sync.aligned.m8n8.x2.shared.b16 {%0,%1}, [%2];"
        : "=r"(r0), "=r"(r1) : "r"(a));
}

__device__ __forceinline__ void mma_bf16_16816(float& c0, float& c1, float& c2, float& c3,
                                               unsigned a0, unsigned a1, unsigned a2, unsigned a3,
                                               unsigned b0, unsigned b1)
{
    asm volatile(
        "mma.sync.aligned.m16n8k16.row.col.f32.bf16.bf16.f32 "
        "{%0,%1,%2,%3}, {%4,%5,%6,%7}, {%8,%9}, {%0,%1,%2,%3};"
        : "+f"(c0), "+f"(c1), "+f"(c2), "+f"(c3)
        : "r"(a0), "r"(a1), "r"(a2), "r"(a3), "r"(b0), "r"(b1));
}

__device__ __forceinline__ void grid_barrier()
{
    __syncthreads();
    if (threadIdx.x == 0) {
        __threadfence();
        unsigned gen = *(volatile unsigned*)&g_bar_gen;
        unsigned t = atomicAdd(&g_bar_cnt, 1u);
        if (t == NCTA - 1) {
            atomicExch(&g_bar_cnt, 0u);
            __threadfence();
            atomicAdd(&g_bar_gen, 1u);
        } else {
            while (*(volatile unsigned*)&g_bar_gen == gen) { }
        }
        __threadfence();
    }
    __syncthreads();
}

// ---------------------------------------------------------------------------
// Persistent recurrence kernel, v6: mma.sync bf16 hi/lo split (3-pass),
// cp.async.bulk chunk streaming (4 x 8KB per stage, mbarrier-signaled).
// grid = 128 CTAs x 512 threads. CTA owns h rows [bid*16, bid*16+16).
// Warp w: tile = w&7 (m_off=16*(tile&3) b, n_off=8*(tile>>2) h),
//         k-group = w>>3 (k in [grp*1024, +1024)).
// ---------------------------------------------------------------------------
extern __shared__ char s_raw[];

__global__ __launch_bounds__(TPB, 1)
void rnn_persistent(const int* __restrict__ tok_all,     // [T_][B_]
                    const float* __restrict__ hidden_w,  // [H_][VH_]
                    const float* __restrict__ hidden_b)  // [H_]
{
    __nv_bfloat16* Whi = (__nv_bfloat16*)s_raw;           // [16][WSTR]
    __nv_bfloat16* Wlo = Whi + HW * WSTR;                 // [16][WSTR]
    __nv_bfloat16* Asm = Wlo + HW * WSTR;                 // [2buf][2grp][2hl][CHBLK]
    float4*  sred = (float4*)(Asm + 2 * 2 * 2 * CHBLK);   // [8 tiles][32 lanes]
    unsigned long long* mbar = (unsigned long long*)(sred + 8 * 32); // [2]

    const int tid  = threadIdx.x;
    const int lane = tid & 31;
    const int wid  = tid >> 5;
    const int h0   = blockIdx.x * HW;

    const unsigned mb0 = smem_u32(&mbar[0]);
    const unsigned mb1 = smem_u32(&mbar[1]);
    if (tid == 0) { mbar_init(mb0, 1); mbar_init(mb1, 1); }

    // --- prologue: split W_hh slice into bf16 hi/lo in SMEM (once) ---
    for (int idx = tid; idx < HW * H_; idx += TPB) {
        int r = idx >> 11;          // /2048
        int k = idx & (H_ - 1);
        float w = hidden_w[(size_t)(h0 + r) * VH_ + V_ + k];
        __nv_bfloat16 hi = __float2bfloat16(w);
        float rem = w - __bfloat162float(hi);
        Whi[r * WSTR + k] = hi;
        Wlo[r * WSTR + k] = __float2bfloat16(rem);
    }
    __syncthreads();

    // warp mapping
    const int tile  = wid & 7;
    const int grp   = wid >> 3;
    const int m_off = 16 * (tile & 3);
    const int n_off = 8 * (tile >> 2);
    const int g  = lane >> 2;         // 0..7
    const int kk = (lane & 3) * 2;    // 0,2,4,6

    // a-side ldmatrix addressing in swizzled chunk blocks:
    // row = m_off + (lane&15); logical 16B unit = 2*ksx + (lane>>4);
    // physical unit = logical ^ (row & 7)
    const int aRow   = m_off + (lane & 15);
    const int aRowB  = aRow * 128;
    const int aXor   = aRow & 7;
    const int aUbase = lane >> 4;

    // b-side (W smem) ldmatrix offset, elems
    const int bOff = (n_off + (lane & 7)) * WSTR + (((lane >> 3) & 1) << 3);

    // epilogue constants (grp 0 warps write)
    const int hI  = h0 + n_off + kk;      // h pair (hI, hI+1)
    const int bI0 = m_off + g;            // b rows bI0, bI0+8
    const float bias0 = hidden_b[hI];
    const float bias1 = hidden_b[hI + 1];
    const float* wr0 = hidden_w + (size_t)hI * VH_;
    const float* wr1 = hidden_w + (size_t)(hI + 1) * VH_;
    // ring-write offset pieces: chunk = hI>>6, byte in block = b*128 + (hI&63)*2
    const int wChunk = hI >> 6;
    const int wColB  = (hI & 63) * 2;

    unsigned ph[2] = {0u, 0u};

    for (int t = 0; t < T_; ++t) {
        float c0 = 0.f, c1 = 0.f, c2 = 0.f, c3 = 0.f;
        const int cur = t & 1, pb = cur ^ 1;

        if (t > 0) {
            // prefetch chunk 0 (both groups, hi+lo) into buffer 0
            if (tid == 0) {
                mbar_expect_tx(mb0, 4 * 8192);
#pragma unroll
                for (int g2 = 0; g2 < 2; ++g2)
#pragma unroll
                    for (int hl = 0; hl < 2; ++hl)
                        bulk_g2s(smem_u32(Asm + (((0 * 2 + g2) * 2 + hl) * CHBLK)),
                                 &g_ring[pb][g2 * NCHG + 0][hl][0], 8192, mb0);
            }

            for (int c = 0; c < NCHG; ++c) {
                const int buf = c & 1;
                mbar_wait(buf ? mb1 : mb0, ph[buf]);
                ph[buf] ^= 1u;

                // issue chunk c+1 into the other buffer (free since chunk c-1's
                // end-of-chunk __syncthreads)
                if (tid == 0 && c + 1 < NCHG) {
                    const int nbuf = (c + 1) & 1;
                    const unsigned mbn = nbuf ? mb1 : mb0;
                    mbar_expect_tx(mbn, 4 * 8192);
#pragma unroll
                    for (int g2 = 0; g2 < 2; ++g2)
#pragma unroll
                        for (int hl = 0; hl < 2; ++hl)
                            bulk_g2s(smem_u32(Asm + (((nbuf * 2 + g2) * 2 + hl) * CHBLK)),
                                     &g_ring[pb][g2 * NCHG + c + 1][hl][0], 8192, mbn);
                }

                const __nv_bfloat16* Ah = Asm + ((buf * 2 + grp) * 2 + 0) * CHBLK;
                const __nv_bfloat16* Al = Ah + CHBLK;
                const unsigned ahBase = smem_u32(Ah) + aRowB;
                const unsigned alBase = smem_u32(Al) + aRowB;
                const int kbase = grp * 1024 + c * BK;

#pragma unroll
                for (int ksx = 0; ksx < BK / 16; ++ksx) {   // 4 k16 steps
                    const unsigned uoff = (unsigned)((((2 * ksx + aUbase) ^ aXor)) << 4);
                    unsigned ah0, ah1, ah2, ah3, al0, al1, al2, al3;
                    unsigned bh0, bh1, bl0, bl1;
                    ldsm_x4(ah0, ah1, ah2, ah3, ahBase + uoff);
                    ldsm_x4(al0, al1, al2, al3, alBase + uoff);
                    const int ko = ksx * 16;
                    ldsm_x2(bh0, bh1, Whi + bOff + kbase + ko);
                    ldsm_x2(bl0, bl1, Wlo + bOff + kbase + ko);

                    mma_bf16_16816(c0, c1, c2, c3, ah0, ah1, ah2, ah3, bh0, bh1);
                    mma_bf16_16816(c0, c1, c2, c3, ah0, ah1, ah2, ah3, bl0, bl1);
                    mma_bf16_16816(c0, c1, c2, c3, al0, al1, al2, al3, bh0, bh1);
                }
                __syncthreads();
            }
        }

        // --- k-split reduction: group 1 stores partials, group 0 accumulates ---
        if (grp == 1) sred[tile * 32 + lane] = make_float4(c0, c1, c2, c3);
        __syncthreads();

        if (grp == 0) {
            float4 o = sred[tile * 32 + lane];
            c0 += o.x; c1 += o.y; c2 += o.z; c3 += o.w;

            float* next = g_states + (size_t)t * B_ * H_;

#pragma unroll
            for (int half = 0; half < 2; ++half) {
                const int b = bI0 + 8 * half;
                const float x0 = half ? c2 : c0;
                const float x1 = half ? c3 : c1;
                int tk = tok_all[t * B_ + b];
                tk = (tk < 0) ? 0 : ((tk >= V_) ? V_ - 1 : tk);
                float v0 = tanhf(x0 + bias0 + wr0[tk]);
                float v1 = tanhf(x1 + bias1 + wr1[tk]);

                *(float2*)(next + (size_t)b * H_ + hI) = make_float2(v0, v1);

                __nv_bfloat16 h0b = __float2bfloat16(v0);
                __nv_bfloat16 h1b = __float2bfloat16(v1);
                __nv_bfloat162 hh; hh.x = h0b; hh.y = h1b;
                __nv_bfloat162 ll;
                ll.x = __float2bfloat16(v0 - __bfloat162float(h0b));
                ll.y = __float2bfloat16(v1 - __bfloat162float(h1b));

                unsigned so = sw128((unsigned)(b * 128 + wColB));
                *(__nv_bfloat162*)((char*)&g_ring[cur][wChunk][0][0] + so) = hh;
                *(__nv_bfloat162*)((char*)&g_ring[cur][wChunk][1][0] + so) = ll;
            }
        }

        grid_barrier();
    }
}

// ---------------------------------------------------------------------------
// Batched output projection (scalar fp32, measured-good ~2.9 ms):
//   out[m, v] = output_b[v] + sum_h S[m,h] * output_w[v,h]
// BM=BN=128, BK=8, 256 threads, 8x8 microtile.
// ---------------------------------------------------------------------------
__global__ void out_gemm_kernel(const float* __restrict__ W,   // [V_][H_]
                                const float* __restrict__ ob,  // [V_]
                                float* __restrict__ out)       // [T_*B_][V_]
{
    __shared__ float As[8][128];  // [k][m]
    __shared__ float Bs[8][128];  // [k][n]

    const float* S = g_states;    // [T_*B_][H_]

    const int tid = threadIdx.x;
    const int m0  = blockIdx.y * 128;
    const int n0  = blockIdx.x * 128;
    const int tx  = tid & 15;
    const int ty  = tid >> 4;
    const int mr  = ty * 8;
    const int nr  = tx * 8;

    float acc[8][8];
#pragma unroll
    for (int i = 0; i < 8; i++)
#pragma unroll
        for (int j = 0; j < 8; j++) acc[i][j] = 0.0f;

    const int lrow = tid >> 1;        // 0..127
    const int lk   = (tid & 1) * 4;   // 0 or 4

    for (int k0 = 0; k0 < H_; k0 += 8) {
        float4 av = *(const float4*)(S + (size_t)(m0 + lrow) * H_ + k0 + lk);
        float4 bv = *(const float4*)(W + (size_t)(n0 + lrow) * H_ + k0 + lk);
        As[lk + 0][lrow] = av.x; As[lk + 1][lrow] = av.y;
        As[lk + 2][lrow] = av.z; As[lk + 3][lrow] = av.w;
        Bs[lk + 0][lrow] = bv.x; Bs[lk + 1][lrow] = bv.y;
        Bs[lk + 2][lrow] = bv.z; Bs[lk + 3][lrow] = bv.w;
        __syncthreads();
#pragma unroll
        for (int kk = 0; kk < 8; kk++) {
            float a[8], b[8];
            *(float4*)&a[0] = *(const float4*)&As[kk][mr];
            *(float4*)&a[4] = *(const float4*)&As[kk][mr + 4];
            *(float4*)&b[0] = *(const float4*)&Bs[kk][nr];
            *(float4*)&b[4] = *(const float4*)&Bs[kk][nr + 4];
#pragma unroll
            for (int i = 0; i < 8; i++)
#pragma unroll
                for (int j = 0; j < 8; j++)
                    acc[i][j] += a[i] * b[j];
        }
        __syncthreads();
    }

#pragma unroll
    for (int i = 0; i < 8; i++) {
        const int m = m0 + mr + i;
#pragma unroll
        for (int j = 0; j < 8; j += 4) {
            const int n = n0 + nr + j;
            float4 o;
            o.x = acc[i][j + 0] + ob[n + 0];
            o.y = acc[i][j + 1] + ob[n + 1];
            o.z = acc[i][j + 2] + ob[n + 2];
            o.w = acc[i][j + 3] + ob[n + 3];
            *(float4*)(out + (size_t)m * V_ + n) = o;
        }
    }
}

// Copy final state (g_states[T_-1]) to the tail of the output buffer.
__global__ void copy_final_state_kernel(float* __restrict__ dst)
{
    const float* src = g_states + (size_t)(T_ - 1) * B_ * H_;
    int idx = blockIdx.x * blockDim.x + threadIdx.x;
    if (idx < B_ * H_) dst[idx] = src[idx];
}

extern "C" void kernel_launch(void* const* d_in, const int* in_sizes, int n_in,
                              void* d_out, int out_size)
{
    const int*   inputs   = (const int*)d_in[0];     // [T_][B_] int32
    const float* hidden_w = (const float*)d_in[1];   // [H_][VH_]
    const float* hidden_b = (const float*)d_in[2];   // [H_]
    const float* output_w = (const float*)d_in[3];   // [V_][H_]
    const float* output_b = (const float*)d_in[4];   // [V_]
    float*       out      = (float*)d_out;

    (void)in_sizes; (void)n_in;

    // Whi+Wlo + A chunk buffers + reduction scratch + mbarriers
    const int smem_bytes = (2 * HW * WSTR + 2 * 2 * 2 * CHBLK) * (int)sizeof(__nv_bfloat16)
                         + 8 * 32 * (int)sizeof(float4) + 2 * (int)sizeof(unsigned long long);
    cudaFuncSetAttribute(rnn_persistent,
                         cudaFuncAttributeMaxDynamicSharedMemorySize, smem_bytes);

    // One persistent launch runs all 128 recurrence steps.
    rnn_persistent<<<NCTA, TPB, smem_bytes>>>(inputs, hidden_w, hidden_b);

    // Batched output projection over all timesteps
    dim3 grid(V_ / 128, (T_ * B_) / 128);
    out_gemm_kernel<<<grid, 256>>>(output_w, output_b, out);

    // Final state, if the output buffer includes it (outputs first, then final_state)
    const size_t outputs_elems = (size_t)T_ * B_ * V_;
    if ((size_t)out_size >= outputs_elems + (size_t)B_ * H_) {
        copy_final_state_kernel<<<(B_ * H_ + 255) / 256, 256>>>(out + outputs_elems);
    }
}